// round 13
// baseline (speedup 1.0000x reference)
#include <cuda_runtime.h>
#include <cuda_bf16.h>

// ---------------------------------------------------------------------------
// GCN 3-layer forward on GB300.
// R13: gemm64 moved to 256 threads/block (same 128-row tile, same smem) —
// doubles warps/SM (8->16) to fix the occupancy-starved latency stall that
// ncu exposed (occ 11.4%, issue 29%, x streamed at only 900GB/s).
// Everything else byte-identical to the 307-308us champion.
// ---------------------------------------------------------------------------

#define N_NODES 100000
#define N_EDGES 1600000
#define SCAN_BS 1024
#define SCAN_NB ((N_NODES + SCAN_BS - 1) / SCAN_BS)

__device__ __align__(16) float  g_h[N_NODES * 64];
__device__ __align__(16) float  g_aggA[N_NODES * 64];
__device__ __align__(16) float  g_aggB[N_NODES * 64];
__device__ float  g_dinv[N_NODES];
__device__ int2   g_sd[N_EDGES];      // packed (src,dst) from input
__device__ int    g_cnt[N_NODES];
__device__ int    g_rowptr[N_NODES + 1];
__device__ int    g_cursor[N_NODES];
__device__ int    g_bsum[SCAN_NB];
__device__ __align__(8) float2 g_epack[N_EDGES];  // CSR: {src bits, coef}
__device__ int    g_is64;

#define FMA2(d, a, b) \
    asm("fma.rn.f32x2 %0, %1, %2, %0;" : "+l"(d) : "l"(a), "l"(b))
#define PACKXX(d, x) \
    asm("mov.b64 %0, {%1, %1};" : "=l"(d) : "f"(x))

// ---------------------------------------------------------------------------
// Prep
// ---------------------------------------------------------------------------
__global__ void detect_zero_kernel(const int* __restrict__ w, int n) {
    int i = blockIdx.x * blockDim.x + threadIdx.x;
    if (i < n) g_cnt[i] = 0;
    if (blockIdx.x == 0) {
        // odd int32 words: int64 -> always 0 (high words); int32 -> src ids.
        __shared__ int nonzero;
        if (threadIdx.x == 0) nonzero = 0;
        __syncthreads();
        if (w[2 * threadIdx.x + 1] != 0) atomicOr(&nonzero, 1);
        __syncthreads();
        if (threadIdx.x == 0) g_is64 = (nonzero == 0) ? 1 : 0;
    }
}

__global__ void hist_kernel(const void* __restrict__ ei, int ne) {
    int e = blockIdx.x * blockDim.x + threadIdx.x;
    if (e >= ne) return;
    int s, d;
    if (g_is64) {
        const long long* p = (const long long*)ei;
        s = (int)p[e];
        d = (int)p[ne + e];
    } else {
        const int* p = (const int*)ei;
        s = p[e];
        d = p[ne + e];
    }
    g_sd[e] = make_int2(s, d);
    atomicAdd(&g_cnt[d], 1);
}

__global__ void scan1_kernel(int n) {   // block-local exclusive scan + dinv
    __shared__ int sm[SCAN_BS];
    int t = threadIdx.x;
    int i = blockIdx.x * SCAN_BS + t;
    int v = (i < n) ? g_cnt[i] : 0;
    sm[t] = v;
    __syncthreads();
    for (int off = 1; off < SCAN_BS; off <<= 1) {
        int u = (t >= off) ? sm[t - off] : 0;
        __syncthreads();
        sm[t] += u;
        __syncthreads();
    }
    if (i < n) {
        g_rowptr[i] = sm[t] - v;
        g_dinv[i]   = rsqrtf((float)v + 1.0f);
    }
    if (t == SCAN_BS - 1) g_bsum[blockIdx.x] = sm[t];
}

// scan3: add cross-block prefix (computed locally by one warp) + init cursor.
// Each 256-thread block spans exactly one scan1 block (1024 % 256 == 0).
__global__ void scan3_kernel(int n, int ne) {
    __shared__ int s_pref;
    const int t = threadIdx.x;
    const int b = (blockIdx.x * 256) / SCAN_BS;   // enclosing scan1 block
    if (t < 32) {
        int v = 0;
        for (int j = t; j < b; j += 32) v += g_bsum[j];
#pragma unroll
        for (int o = 16; o; o >>= 1) v += __shfl_down_sync(0xffffffffu, v, o);
        if (t == 0) s_pref = v;
    }
    __syncthreads();
    int i = blockIdx.x * 256 + t;
    if (i < n) {
        int r = g_rowptr[i] + s_pref;
        g_rowptr[i] = r;
        g_cursor[i] = r;
    }
    if (i == 0) g_rowptr[n] = ne;
}

__global__ void place_kernel(int ne) {
    int e = blockIdx.x * blockDim.x + threadIdx.x;
    if (e >= ne) return;
    int2 sd = g_sd[e];
    int pos = atomicAdd(&g_cursor[sd.y], 1);
    g_epack[pos] = make_float2(__int_as_float(sd.x), g_dinv[sd.x] * g_dinv[sd.y]);
}

// ---------------------------------------------------------------------------
// Register-blocked GEMM, DOUT=64, 256 threads: h = relu?(in) @ W.
// cg=tid&7 (cols cg*4..+3 and 32+cg*4..+3), tr=tid>>3 (0..31; rows tr+32j,
// j=0..3). 16 f32x2 accumulators (4 rows x 4 col-pairs).
// Same smem layout/footprint as the 128-thread version -> same blocks/SM but
// 2x warps/SM for latency hiding (staging LDG MLP + compute LDS chains).
// XS = DIN+4 keeps float4 row staging 16B-aligned; x broadcast reads hit
// banks 4 apart (XS=132/68 -> %32 = 4) — conflict-free.
// ---------------------------------------------------------------------------
template <int DIN, bool RELU_IN>
__global__ void __launch_bounds__(256) gemm64_kernel(const float* __restrict__ in,
                                                     const float* __restrict__ W,
                                                     float* __restrict__ h_out,
                                                     int n)
{
    constexpr int DOUT = 64;
    constexpr int TILE_R = 128;
    constexpr int XS = DIN + 4;
    extern __shared__ float sm[];
    float* sW = sm;                 // DIN*DOUT
    float* sX = sm + DIN * DOUT;    // TILE_R*XS

    const int tid  = threadIdx.x;
    const int row0 = blockIdx.x * TILE_R;

    const float4* Wv  = (const float4*)W;
    float4*       sWv = (float4*)sW;
    for (int i = tid; i < DIN * DOUT / 4; i += 256) sWv[i] = Wv[i];

    for (int i = tid; i < TILE_R * DIN / 4; i += 256) {
        int r  = i / (DIN / 4);
        int kq = i - r * (DIN / 4);
        int gr = row0 + r;
        float4 v = make_float4(0.f, 0.f, 0.f, 0.f);
        if (gr < n) v = ((const float4*)in)[gr * (DIN / 4) + kq];
        if (RELU_IN) {
            v.x = fmaxf(v.x, 0.f); v.y = fmaxf(v.y, 0.f);
            v.z = fmaxf(v.z, 0.f); v.w = fmaxf(v.w, 0.f);
        }
        *(float4*)&sX[r * XS + kq * 4] = v;
    }
    __syncthreads();

    const int cg = tid & 7;
    const int tr = tid >> 3;        // 0..31; rows tr + 32j

    unsigned long long acc[4][4];
#pragma unroll
    for (int j = 0; j < 4; j++)
#pragma unroll
        for (int p = 0; p < 4; p++) acc[j][p] = 0ULL;

    const float* xbase = sX + tr * XS;
    const ulonglong2* wv = (const ulonglong2*)sW;

#pragma unroll 4
    for (int k = 0; k < DIN; k++) {
        // two conflict-free LDS.128: 8 lanes x 16B contiguous per instruction
        ulonglong2 wA = wv[k * (DOUT / 4) + cg];       // cols cg*4..cg*4+3
        ulonglong2 wB = wv[k * (DOUT / 4) + 8 + cg];   // cols 32+cg*4..+3
#pragma unroll
        for (int j = 0; j < 4; j++) {
            float xv = xbase[j * 32 * XS + k];
            unsigned long long xx;
            PACKXX(xx, xv);
            FMA2(acc[j][0], xx, wA.x);
            FMA2(acc[j][1], xx, wA.y);
            FMA2(acc[j][2], xx, wB.x);
            FMA2(acc[j][3], xx, wB.y);
        }
    }

#pragma unroll
    for (int j = 0; j < 4; j++) {
        int r = row0 + tr + 32 * j;
        if (r < n) {
            ulonglong2* o = (ulonglong2*)&h_out[r * DOUT + cg * 4];
            o[0] = make_ulonglong2(acc[j][0], acc[j][1]);          // cols cg*4..
            o[8] = make_ulonglong2(acc[j][2], acc[j][3]);          // cols 32+cg*4..
        }
    }
}

// ---------------------------------------------------------------------------
// GEMM for DOUT=40 (layer 3) — smem-walk version (small share of runtime).
// ---------------------------------------------------------------------------
template <int DIN, int DOUT, int CGROUPS, int TILE_R, bool RELU_IN>
__global__ void gemm_kernel(const float* __restrict__ in,
                            const float* __restrict__ W,
                            float* __restrict__ h_out,
                            int n)
{
    constexpr int CP = DOUT / CGROUPS;
    constexpr int XS = DIN + 1;
    extern __shared__ float sm[];
    float* sW = sm;
    float* sX = sm + DIN * DOUT;

    const int tid  = threadIdx.x;
    const int nthr = blockDim.x;
    const int row0 = blockIdx.x * TILE_R;

    for (int i = tid; i < DIN * DOUT; i += nthr) sW[i] = W[i];
    for (int i = tid; i < TILE_R * DIN; i += nthr) {
        int r = i / DIN;
        int k = i - r * DIN;
        int gr = row0 + r;
        float v = 0.0f;
        if (gr < n) v = in[gr * DIN + k];
        if (RELU_IN) v = fmaxf(v, 0.0f);
        sX[r * XS + k] = v;
    }
    __syncthreads();

    const int rl = tid / CGROUPS;
    const int cg = tid - rl * CGROUPS;
    const int c0 = cg * CP;

    float acc[CP];
#pragma unroll
    for (int j = 0; j < CP; j++) acc[j] = 0.0f;

    const float* xrow = &sX[rl * XS];
#pragma unroll 4
    for (int k = 0; k < DIN; k++) {
        float xv = xrow[k];
        const float4* wrow = reinterpret_cast<const float4*>(&sW[k * DOUT + c0]);
#pragma unroll
        for (int j4 = 0; j4 < CP / 4; j4++) {
            float4 w = wrow[j4];
            acc[j4 * 4 + 0] = fmaf(xv, w.x, acc[j4 * 4 + 0]);
            acc[j4 * 4 + 1] = fmaf(xv, w.y, acc[j4 * 4 + 1]);
            acc[j4 * 4 + 2] = fmaf(xv, w.z, acc[j4 * 4 + 2]);
            acc[j4 * 4 + 3] = fmaf(xv, w.w, acc[j4 * 4 + 3]);
        }
    }

    const int r = row0 + rl;
    if (r < n) {
#pragma unroll
        for (int j4 = 0; j4 < CP / 4; j4++) {
            float4 hv = make_float4(acc[j4 * 4 + 0], acc[j4 * 4 + 1],
                                    acc[j4 * 4 + 2], acc[j4 * 4 + 3]);
            *reinterpret_cast<float4*>(&h_out[r * DOUT + c0 + j4 * 4]) = hv;
        }
    }
}

// ---------------------------------------------------------------------------
// Aggregation DOUT=64: warp per node, 2 edges/iter (half-warps), float4 lanes.
// (measured-best form)
// ---------------------------------------------------------------------------
__global__ void aggregate64_kernel(const float* __restrict__ h,
                                   const float* __restrict__ bias,
                                   float* __restrict__ out,
                                   int n)
{
    int w = (blockIdx.x * blockDim.x + threadIdx.x) >> 5;
    if (w >= n) return;
    int lane = threadIdx.x & 31;
    int half = lane >> 4;
    int sub  = lane & 15;

    int c0 = g_rowptr[w];
    int c1 = g_rowptr[w + 1];

    const float4* hp4 = (const float4*)h;   // 16 float4 per row
    float4 acc = make_float4(0.f, 0.f, 0.f, 0.f);

#pragma unroll 2
    for (int i = c0; i < c1; i += 2) {
        int e = i + half;
        if (e < c1) {
            float2 pk = g_epack[e];
            int   s = __float_as_int(pk.x);
            float c = pk.y;
            float4 v = hp4[s * 16 + sub];
            acc.x = fmaf(v.x, c, acc.x);
            acc.y = fmaf(v.y, c, acc.y);
            acc.z = fmaf(v.z, c, acc.z);
            acc.w = fmaf(v.w, c, acc.w);
        }
    }
    // combine the two half-warp partial sums
    acc.x += __shfl_xor_sync(0xffffffffu, acc.x, 16);
    acc.y += __shfl_xor_sync(0xffffffffu, acc.y, 16);
    acc.z += __shfl_xor_sync(0xffffffffu, acc.z, 16);
    acc.w += __shfl_xor_sync(0xffffffffu, acc.w, 16);

    float di  = g_dinv[w];
    float di2 = di * di;
    float4 hs = hp4[w * 16 + sub];
    float4 bv = ((const float4*)bias)[sub];
    float4 r;
    r.x = fmaf(hs.x, di2, acc.x) + bv.x;
    r.y = fmaf(hs.y, di2, acc.y) + bv.y;
    r.z = fmaf(hs.z, di2, acc.z) + bv.z;
    r.w = fmaf(hs.w, di2, acc.w) + bv.w;
    if (half == 0) ((float4*)out)[w * 16 + sub] = r;
}

// ---------------------------------------------------------------------------
// Aggregation DOUT=40: warp per node; col=lane plus col=32+lane for lane<8.
// (measured-best form)
// ---------------------------------------------------------------------------
__global__ void aggregate40_kernel(const float* __restrict__ h,
                                   const float* __restrict__ bias,
                                   float* __restrict__ out,
                                   int n)
{
    int w = (blockIdx.x * blockDim.x + threadIdx.x) >> 5;
    if (w >= n) return;
    int lane = threadIdx.x & 31;

    int c0 = g_rowptr[w];
    int c1 = g_rowptr[w + 1];
    bool hi = (lane < 8);

    float a0 = 0.0f, a1 = 0.0f;
    for (int i = c0; i < c1; i++) {
        float2 pk = g_epack[i];
        int   s = __float_as_int(pk.x);
        float c = pk.y;
        const float* hr = &h[s * 40];
        a0 = fmaf(hr[lane], c, a0);
        if (hi) a1 = fmaf(hr[32 + lane], c, a1);
    }

    float di  = g_dinv[w];
    float di2 = di * di;
    const float* hs = &h[w * 40];
    out[w * 40 + lane] = fmaf(hs[lane], di2, a0) + bias[lane];
    if (hi)
        out[w * 40 + 32 + lane] = fmaf(hs[32 + lane], di2, a1) + bias[32 + lane];
}

// ---------------------------------------------------------------------------
// Launch (single stream; gemm1 at launch slot 4 for ncu visibility)
// ---------------------------------------------------------------------------
extern "C" void kernel_launch(void* const* d_in, const int* in_sizes, int n_in,
                              void* d_out, int out_size)
{
    const float* x  = (const float*)d_in[0];
    const void*  ei = d_in[1];
    const float* W1 = (const float*)d_in[2];
    const float* b1 = (const float*)d_in[3];
    const float* W2 = (const float*)d_in[4];
    const float* b2 = (const float*)d_in[5];
    const float* W3 = (const float*)d_in[6];
    const float* b3 = (const float*)d_in[7];
    float* out = (float*)d_out;

    const int N = in_sizes[0] / 128;   // 100000
    const int E = in_sizes[1] / 2;     // 1600000

    float *h, *aggA, *aggB;
    cudaGetSymbolAddress((void**)&h,    g_h);
    cudaGetSymbolAddress((void**)&aggA, g_aggA);
    cudaGetSymbolAddress((void**)&aggB, g_aggB);

    constexpr int TRB = 128;                       // big-GEMM row tile
    const int g2_grid  = (N + TRB - 1) / TRB;
    const int agg_grid = (N * 32 + 255) / 256;
    const int smem1 = (128 * 64 + TRB * (128 + 4)) * (int)sizeof(float);  // ~100.4KB
    const int smem2 = (64 * 64 + TRB * (64 + 4)) * (int)sizeof(float);    // ~51.2KB
    cudaFuncSetAttribute(gemm64_kernel<128, false>,
                         cudaFuncAttributeMaxDynamicSharedMemorySize, smem1);
    cudaFuncSetAttribute(gemm64_kernel<64, true>,
                         cudaFuncAttributeMaxDynamicSharedMemorySize, smem2);

    // --- prep (launches 1-3) ---
    detect_zero_kernel<<<(N + 255) / 256, 256>>>((const int*)ei, N);
    hist_kernel<<<(E + 255) / 256, 256>>>(ei, E);
    const int nb = (N + SCAN_BS - 1) / SCAN_BS;
    scan1_kernel<<<nb, SCAN_BS>>>(N);

    // --- launch 4: GEMM1 (independent of CSR prep; ncu captures slot 4) ---
    gemm64_kernel<128, false><<<g2_grid, 256, smem1>>>(x, W1, h, N);

    // --- prep tail (launches 5-6) ---
    scan3_kernel<<<(N + 255) / 256, 256>>>(N, E);
    place_kernel<<<(E + 255) / 256, 256>>>(E);

    // --- layer 1 aggregation ---
    aggregate64_kernel<<<agg_grid, 256>>>(h, b1, aggA, N);

    // --- layer 2: 64 -> 64 ---
    gemm64_kernel<64, true><<<g2_grid, 256, smem2>>>(aggA, W2, h, N);
    aggregate64_kernel<<<agg_grid, 256>>>(h, b2, aggB, N);

    // --- layer 3: 64 -> 40 ---
    constexpr int TR3 = 64;
    const int g3_grid = (N + TR3 - 1) / TR3;
    const int smem3 = (64 * 40 + TR3 * (64 + 1)) * (int)sizeof(float);
    gemm_kernel<64, 40, 5, TR3, true><<<g3_grid, TR3 * 5, smem3>>>(aggB, W3, h, N);
    aggregate40_kernel<<<agg_grid, 256>>>(h, b3, out, N);
}

// round 15
// speedup vs baseline: 1.0799x; 1.0799x over previous
#include <cuda_runtime.h>
#include <cuda_bf16.h>
#include <cstdint>

// ---------------------------------------------------------------------------
// GCN 3-layer forward on GB300.
// R15 (= R14 + missing <cstdint>): cp.async double-buffered k-chunk GEMM
// (continuous DRAM streaming, smaller smem -> 3-4 blocks/SM). Relu folded
// into aggregate64 epilogue. Prep + aggregation byte-identical to champion.
// ---------------------------------------------------------------------------

#define N_NODES 100000
#define N_EDGES 1600000
#define SCAN_BS 1024
#define SCAN_NB ((N_NODES + SCAN_BS - 1) / SCAN_BS)

__device__ __align__(16) float  g_h[N_NODES * 64];
__device__ __align__(16) float  g_aggA[N_NODES * 64];
__device__ __align__(16) float  g_aggB[N_NODES * 64];
__device__ float  g_dinv[N_NODES];
__device__ int2   g_sd[N_EDGES];      // packed (src,dst) from input
__device__ int    g_cnt[N_NODES];
__device__ int    g_rowptr[N_NODES + 1];
__device__ int    g_cursor[N_NODES];
__device__ int    g_bsum[SCAN_NB];
__device__ __align__(8) float2 g_epack[N_EDGES];  // CSR: {src bits, coef}
__device__ int    g_is64;

#define FMA2(d, a, b) \
    asm("fma.rn.f32x2 %0, %1, %2, %0;" : "+l"(d) : "l"(a), "l"(b))
#define PACKXX(d, x) \
    asm("mov.b64 %0, {%1, %1};" : "=l"(d) : "f"(x))
#define CP_ASYNC16(dst, src) \
    asm volatile("cp.async.ca.shared.global [%0], [%1], 16;" \
                 :: "r"(dst), "l"(src) : "memory")
#define CP_COMMIT() asm volatile("cp.async.commit_group;" ::: "memory")
#define CP_WAIT(nn) asm volatile("cp.async.wait_group %0;" :: "n"(nn) : "memory")

// ---------------------------------------------------------------------------
// Prep (byte-identical to champion)
// ---------------------------------------------------------------------------
__global__ void detect_zero_kernel(const int* __restrict__ w, int n) {
    int i = blockIdx.x * blockDim.x + threadIdx.x;
    if (i < n) g_cnt[i] = 0;
    if (blockIdx.x == 0) {
        __shared__ int nonzero;
        if (threadIdx.x == 0) nonzero = 0;
        __syncthreads();
        if (w[2 * threadIdx.x + 1] != 0) atomicOr(&nonzero, 1);
        __syncthreads();
        if (threadIdx.x == 0) g_is64 = (nonzero == 0) ? 1 : 0;
    }
}

__global__ void hist_kernel(const void* __restrict__ ei, int ne) {
    int e = blockIdx.x * blockDim.x + threadIdx.x;
    if (e >= ne) return;
    int s, d;
    if (g_is64) {
        const long long* p = (const long long*)ei;
        s = (int)p[e];
        d = (int)p[ne + e];
    } else {
        const int* p = (const int*)ei;
        s = p[e];
        d = p[ne + e];
    }
    g_sd[e] = make_int2(s, d);
    atomicAdd(&g_cnt[d], 1);
}

__global__ void scan1_kernel(int n) {
    __shared__ int sm[SCAN_BS];
    int t = threadIdx.x;
    int i = blockIdx.x * SCAN_BS + t;
    int v = (i < n) ? g_cnt[i] : 0;
    sm[t] = v;
    __syncthreads();
    for (int off = 1; off < SCAN_BS; off <<= 1) {
        int u = (t >= off) ? sm[t - off] : 0;
        __syncthreads();
        sm[t] += u;
        __syncthreads();
    }
    if (i < n) {
        g_rowptr[i] = sm[t] - v;
        g_dinv[i]   = rsqrtf((float)v + 1.0f);
    }
    if (t == SCAN_BS - 1) g_bsum[blockIdx.x] = sm[t];
}

__global__ void scan3_kernel(int n, int ne) {
    __shared__ int s_pref;
    const int t = threadIdx.x;
    const int b = (blockIdx.x * 256) / SCAN_BS;
    if (t < 32) {
        int v = 0;
        for (int j = t; j < b; j += 32) v += g_bsum[j];
#pragma unroll
        for (int o = 16; o; o >>= 1) v += __shfl_down_sync(0xffffffffu, v, o);
        if (t == 0) s_pref = v;
    }
    __syncthreads();
    int i = blockIdx.x * 256 + t;
    if (i < n) {
        int r = g_rowptr[i] + s_pref;
        g_rowptr[i] = r;
        g_cursor[i] = r;
    }
    if (i == 0) g_rowptr[n] = ne;
}

__global__ void place_kernel(int ne) {
    int e = blockIdx.x * blockDim.x + threadIdx.x;
    if (e >= ne) return;
    int2 sd = g_sd[e];
    int pos = atomicAdd(&g_cursor[sd.y], 1);
    g_epack[pos] = make_float2(__int_as_float(sd.x), g_dinv[sd.x] * g_dinv[sd.y]);
}

// ---------------------------------------------------------------------------
// Pipelined register-blocked GEMM, DOUT=64, 128 threads.
// x staged in KC=32-column chunks, double-buffered via cp.async — DRAM
// streaming overlaps compute. Compute core identical to the 307us champion:
// cg=tid&7, tr=tid>>3, 8 rows x 8 cols per thread, FFMA2.
// ---------------------------------------------------------------------------
template <int DIN>
__global__ void __launch_bounds__(128) gemm64p_kernel(const float* __restrict__ in,
                                                      const float* __restrict__ W,
                                                      float* __restrict__ h_out,
                                                      int n)
{
    constexpr int DOUT = 64;
    constexpr int TILE_R = 128;
    constexpr int KC = 32;               // k-chunk columns
    constexpr int XS = KC + 4;           // padded chunk row stride (36 floats)
    constexpr int NCH = DIN / KC;        // 4 (DIN=128) or 2 (DIN=64)
    constexpr int CHUNK_V4 = TILE_R * KC / 4;   // 1024 float4 per chunk

    extern __shared__ float sm[];
    float* sW = sm;                       // DIN*DOUT floats
    float* sX = sm + DIN * DOUT;          // 2 * TILE_R * XS floats

    const int tid  = threadIdx.x;
    const int row0 = blockIdx.x * TILE_R;
    const unsigned int sx_base = (unsigned int)__cvta_generic_to_shared(sX);

    // Stage W (all of it) with plain float4 loads.
    const float4* Wv  = (const float4*)W;
    float4*       sWv = (float4*)sW;
    for (int i = tid; i < DIN * DOUT / 4; i += 128) sWv[i] = Wv[i];

    // Stage one x chunk: rows row0..row0+127, cols ck*KC..+31.
    auto stage = [&](int ck, int buf) {
#pragma unroll
        for (int i = tid; i < CHUNK_V4; i += 128) {        // 8 iters
            int r = i >> 3;                                 // KC/4 = 8
            int q = i & 7;
            int gr = row0 + r;
            if (gr < n) {
                unsigned int dst = sx_base +
                    (unsigned int)((buf * TILE_R * XS + r * XS + q * 4) * 4);
                const float* src = &in[gr * DIN + ck * KC + q * 4];
                CP_ASYNC16(dst, src);
            }
        }
        CP_COMMIT();
    };

    stage(0, 0);

    const int cg = tid & 7;
    const int tr = tid >> 3;

    unsigned long long acc[8][4];
#pragma unroll
    for (int j = 0; j < 8; j++)
#pragma unroll
        for (int p = 0; p < 4; p++) acc[j][p] = 0ULL;

    const ulonglong2* wv = (const ulonglong2*)sW;

    for (int ck = 0; ck < NCH; ck++) {
        if (ck + 1 < NCH) {
            stage(ck + 1, (ck + 1) & 1);
            CP_WAIT(1);                   // chunk ck resident (ck+1 in flight)
        } else {
            CP_WAIT(0);
        }
        __syncthreads();

        const float* xbase = sX + (ck & 1) * TILE_R * XS + tr * XS;
#pragma unroll
        for (int k = 0; k < KC; k++) {
            ulonglong2 wA = wv[(ck * KC + k) * (DOUT / 4) + cg];
            ulonglong2 wB = wv[(ck * KC + k) * (DOUT / 4) + 8 + cg];
#pragma unroll
            for (int j = 0; j < 8; j++) {
                float xv = xbase[j * 16 * XS + k];
                unsigned long long xx;
                PACKXX(xx, xv);
                FMA2(acc[j][0], xx, wA.x);
                FMA2(acc[j][1], xx, wA.y);
                FMA2(acc[j][2], xx, wB.x);
                FMA2(acc[j][3], xx, wB.y);
            }
        }
        __syncthreads();                  // buffer reuse fence
    }

#pragma unroll
    for (int j = 0; j < 8; j++) {
        int r = row0 + tr + 16 * j;
        if (r < n) {
            ulonglong2* o = (ulonglong2*)&h_out[r * DOUT + cg * 4];
            o[0] = make_ulonglong2(acc[j][0], acc[j][1]);
            o[8] = make_ulonglong2(acc[j][2], acc[j][3]);
        }
    }
}

// ---------------------------------------------------------------------------
// GEMM for DOUT=40 (layer 3) — smem-walk version. Input already relu'd.
// ---------------------------------------------------------------------------
template <int DIN, int DOUT, int CGROUPS, int TILE_R>
__global__ void gemm_kernel(const float* __restrict__ in,
                            const float* __restrict__ W,
                            float* __restrict__ h_out,
                            int n)
{
    constexpr int CP = DOUT / CGROUPS;
    constexpr int XS = DIN + 1;
    extern __shared__ float sm[];
    float* sW = sm;
    float* sX = sm + DIN * DOUT;

    const int tid  = threadIdx.x;
    const int nthr = blockDim.x;
    const int row0 = blockIdx.x * TILE_R;

    for (int i = tid; i < DIN * DOUT; i += nthr) sW[i] = W[i];
    for (int i = tid; i < TILE_R * DIN; i += nthr) {
        int r = i / DIN;
        int k = i - r * DIN;
        int gr = row0 + r;
        float v = 0.0f;
        if (gr < n) v = in[gr * DIN + k];
        sX[r * XS + k] = v;
    }
    __syncthreads();

    const int rl = tid / CGROUPS;
    const int cg = tid - rl * CGROUPS;
    const int c0 = cg * CP;

    float acc[CP];
#pragma unroll
    for (int j = 0; j < CP; j++) acc[j] = 0.0f;

    const float* xrow = &sX[rl * XS];
#pragma unroll 4
    for (int k = 0; k < DIN; k++) {
        float xv = xrow[k];
        const float4* wrow = reinterpret_cast<const float4*>(&sW[k * DOUT + c0]);
#pragma unroll
        for (int j4 = 0; j4 < CP / 4; j4++) {
            float4 w = wrow[j4];
            acc[j4 * 4 + 0] = fmaf(xv, w.x, acc[j4 * 4 + 0]);
            acc[j4 * 4 + 1] = fmaf(xv, w.y, acc[j4 * 4 + 1]);
            acc[j4 * 4 + 2] = fmaf(xv, w.z, acc[j4 * 4 + 2]);
            acc[j4 * 4 + 3] = fmaf(xv, w.w, acc[j4 * 4 + 3]);
        }
    }

    const int r = row0 + rl;
    if (r < n) {
#pragma unroll
        for (int j4 = 0; j4 < CP / 4; j4++) {
            float4 hv = make_float4(acc[j4 * 4 + 0], acc[j4 * 4 + 1],
                                    acc[j4 * 4 + 2], acc[j4 * 4 + 3]);
            *reinterpret_cast<float4*>(&h_out[r * DOUT + c0 + j4 * 4]) = hv;
        }
    }
}

// ---------------------------------------------------------------------------
// Aggregation DOUT=64 (+relu in epilogue — consumed by the next layer which
// always takes relu of this layer's output).
// ---------------------------------------------------------------------------
__global__ void aggregate64_kernel(const float* __restrict__ h,
                                   const float* __restrict__ bias,
                                   float* __restrict__ out,
                                   int n)
{
    int w = (blockIdx.x * blockDim.x + threadIdx.x) >> 5;
    if (w >= n) return;
    int lane = threadIdx.x & 31;
    int half = lane >> 4;
    int sub  = lane & 15;

    int c0 = g_rowptr[w];
    int c1 = g_rowptr[w + 1];

    const float4* hp4 = (const float4*)h;
    float4 acc = make_float4(0.f, 0.f, 0.f, 0.f);

#pragma unroll 2
    for (int i = c0; i < c1; i += 2) {
        int e = i + half;
        if (e < c1) {
            float2 pk = g_epack[e];
            int   s = __float_as_int(pk.x);
            float c = pk.y;
            float4 v = hp4[s * 16 + sub];
            acc.x = fmaf(v.x, c, acc.x);
            acc.y = fmaf(v.y, c, acc.y);
            acc.z = fmaf(v.z, c, acc.z);
            acc.w = fmaf(v.w, c, acc.w);
        }
    }
    acc.x += __shfl_xor_sync(0xffffffffu, acc.x, 16);
    acc.y += __shfl_xor_sync(0xffffffffu, acc.y, 16);
    acc.z += __shfl_xor_sync(0xffffffffu, acc.z, 16);
    acc.w += __shfl_xor_sync(0xffffffffu, acc.w, 16);

    float di  = g_dinv[w];
    float di2 = di * di;
    float4 hs = hp4[w * 16 + sub];
    float4 bv = ((const float4*)bias)[sub];
    float4 r;
    r.x = fmaxf(fmaf(hs.x, di2, acc.x) + bv.x, 0.f);
    r.y = fmaxf(fmaf(hs.y, di2, acc.y) + bv.y, 0.f);
    r.z = fmaxf(fmaf(hs.z, di2, acc.z) + bv.z, 0.f);
    r.w = fmaxf(fmaf(hs.w, di2, acc.w) + bv.w, 0.f);
    if (half == 0) ((float4*)out)[w * 16 + sub] = r;
}

// ---------------------------------------------------------------------------
// Aggregation DOUT=40 (final output — NO relu).
// ---------------------------------------------------------------------------
__global__ void aggregate40_kernel(const float* __restrict__ h,
                                   const float* __restrict__ bias,
                                   float* __restrict__ out,
                                   int n)
{
    int w = (blockIdx.x * blockDim.x + threadIdx.x) >> 5;
    if (w >= n) return;
    int lane = threadIdx.x & 31;

    int c0 = g_rowptr[w];
    int c1 = g_rowptr[w + 1];
    bool hi = (lane < 8);

    float a0 = 0.0f, a1 = 0.0f;
    for (int i = c0; i < c1; i++) {
        float2 pk = g_epack[i];
        int   s = __float_as_int(pk.x);
        float c = pk.y;
        const float* hr = &h[s * 40];
        a0 = fmaf(hr[lane], c, a0);
        if (hi) a1 = fmaf(hr[32 + lane], c, a1);
    }

    float di  = g_dinv[w];
    float di2 = di * di;
    const float* hs = &h[w * 40];
    out[w * 40 + lane] = fmaf(hs[lane], di2, a0) + bias[lane];
    if (hi)
        out[w * 40 + 32 + lane] = fmaf(hs[32 + lane], di2, a1) + bias[32 + lane];
}

// ---------------------------------------------------------------------------
// Launch (single stream; gemm1 at launch slot 4 for ncu visibility)
// ---------------------------------------------------------------------------
extern "C" void kernel_launch(void* const* d_in, const int* in_sizes, int n_in,
                              void* d_out, int out_size)
{
    const float* x  = (const float*)d_in[0];
    const void*  ei = d_in[1];
    const float* W1 = (const float*)d_in[2];
    const float* b1 = (const float*)d_in[3];
    const float* W2 = (const float*)d_in[4];
    const float* b2 = (const float*)d_in[5];
    const float* W3 = (const float*)d_in[6];
    const float* b3 = (const float*)d_in[7];
    float* out = (float*)d_out;

    const int N = in_sizes[0] / 128;   // 100000
    const int E = in_sizes[1] / 2;     // 1600000

    float *h, *aggA, *aggB;
    cudaGetSymbolAddress((void**)&h,    g_h);
    cudaGetSymbolAddress((void**)&aggA, g_aggA);
    cudaGetSymbolAddress((void**)&aggB, g_aggB);

    constexpr int TRB = 128;
    const int g2_grid  = (N + TRB - 1) / TRB;
    const int agg_grid = (N * 32 + 255) / 256;
    // smem: W + 2 chunk buffers (TILE_R * 36 floats each)
    const int smem1 = (128 * 64 + 2 * TRB * 36) * (int)sizeof(float);  // 68KB
    const int smem2 = (64 * 64 + 2 * TRB * 36) * (int)sizeof(float);   // 52KB
    cudaFuncSetAttribute(gemm64p_kernel<128>,
                         cudaFuncAttributeMaxDynamicSharedMemorySize, smem1);
    cudaFuncSetAttribute(gemm64p_kernel<64>,
                         cudaFuncAttributeMaxDynamicSharedMemorySize, smem2);

    // --- prep (launches 1-3) ---
    detect_zero_kernel<<<(N + 255) / 256, 256>>>((const int*)ei, N);
    hist_kernel<<<(E + 255) / 256, 256>>>(ei, E);
    const int nb = (N + SCAN_BS - 1) / SCAN_BS;
    scan1_kernel<<<nb, SCAN_BS>>>(N);

    // --- launch 4: GEMM1 (independent of CSR prep; ncu captures slot 4) ---
    gemm64p_kernel<128><<<g2_grid, 128, smem1>>>(x, W1, h, N);

    // --- prep tail (launches 5-6) ---
    scan3_kernel<<<(N + 255) / 256, 256>>>(N, E);
    place_kernel<<<(E + 255) / 256, 256>>>(E);

    // --- layer 1 aggregation (writes relu'd aggA) ---
    aggregate64_kernel<<<agg_grid, 256>>>(h, b1, aggA, N);

    // --- layer 2: 64 -> 64 ---
    gemm64p_kernel<64><<<g2_grid, 128, smem2>>>(aggA, W2, h, N);
    aggregate64_kernel<<<agg_grid, 256>>>(h, b2, aggB, N);

    // --- layer 3: 64 -> 40 (aggB already relu'd) ---
    constexpr int TR3 = 64;
    const int g3_grid = (N + TR3 - 1) / TR3;
    const int smem3 = (64 * 40 + TR3 * (64 + 1)) * (int)sizeof(float);
    gemm_kernel<64, 40, 5, TR3><<<g3_grid, TR3 * 5, smem3>>>(aggB, W3, h, N);
    aggregate40_kernel<<<agg_grid, 256>>>(h, b3, out, N);
}